// round 10
// baseline (speedup 1.0000x reference)
#include <cuda_runtime.h>
#include <cstdint>

// Problem constants (BertTagger CRF): B=512, T=512, K=128
#define BB 512
#define TT 512
#define KK 128
#define START_TAG 126
#define STOP_TAG 127
#define NTHR 512   // 4 threads per tag j (k-split quarters)

__device__ float g_absdiff[BB];
__device__ int   g_order[BB];
__device__ float g_c;       // static per-step scale: log(max_j sum_k exp(trans[j,k])) + slack

typedef unsigned long long ull;

__device__ __forceinline__ ull ffma2(ull a, ull b, ull c) {
    ull d;
    asm("fma.rn.f32x2 %0, %1, %2, %3;" : "=l"(d) : "l"(a), "l"(b), "l"(c));
    return d;
}
__device__ __forceinline__ ull addf2(ull a, ull b) {
    ull d;
    asm("add.rn.f32x2 %0, %1, %2;" : "=l"(d) : "l"(a), "l"(b));
    return d;
}
__device__ __forceinline__ ull packf2(float x, float y) {
    ull d;
    asm("mov.b64 %0, {%1, %2};" : "=l"(d) : "f"(x), "f"(y));
    return d;
}
__device__ __forceinline__ void unpackf2(ull v, float& x, float& y) {
    asm("mov.b64 {%0, %1}, %2;" : "=f"(x), "=f"(y) : "l"(v));
}

// -------- counting-sort ordering: longest sequences get lowest blockIdx ------
__global__ void order_kernel(const int* __restrict__ lengths) {
    __shared__ int hist[TT];
    __shared__ int sfx[TT];
    __shared__ int cur[TT];
    int b = threadIdx.x;
    hist[b] = 0; cur[b] = 0;
    __syncthreads();
    int len = lengths[b];
    int bin = len - 1;
    atomicAdd(&hist[bin], 1);
    __syncthreads();
    sfx[b] = hist[b];
    __syncthreads();
    #pragma unroll
    for (int d = 1; d < TT; d <<= 1) {
        int v = (b + d < TT) ? sfx[b + d] : 0;
        __syncthreads();
        sfx[b] += v;
        __syncthreads();
    }
    int base = (bin < TT - 1) ? sfx[bin + 1] : 0;
    int pos = base + atomicAdd(&cur[bin], 1);
    g_order[pos] = b;
}

// -------- static scale: c = log(max_j sum_k exp(trans[j,k])) + 2.5 ----------
__global__ void shat_kernel(const float* __restrict__ trans) {
    __shared__ float red[4];
    int j = threadIdx.x;  // 128 threads
    float s = 0.0f;
    #pragma unroll 8
    for (int k = 0; k < KK; k++) s += __expf(trans[j * KK + k]);
    #pragma unroll
    for (int o = 16; o > 0; o >>= 1)
        s = fmaxf(s, __shfl_xor_sync(0xffffffffu, s, o));
    if ((j & 31) == 0) red[j >> 5] = s;
    __syncthreads();
    if (j == 0) {
        float mx = fmaxf(fmaxf(red[0], red[1]), fmaxf(red[2], red[3]));
        g_c = __logf(mx) + 2.5f;
    }
}

// -------- dummy 3rd launch so crf_kernel is the 4th (ncu captures launch #4) --
__global__ void zinit_kernel() {
    g_absdiff[threadIdx.x + blockIdx.x * blockDim.x] = 0.0f;
}

// -------- block reductions (512 threads, 16 warps) --------
__device__ __forceinline__ float block_max16(float v, volatile float* red) {
    #pragma unroll
    for (int o = 16; o > 0; o >>= 1)
        v = fmaxf(v, __shfl_xor_sync(0xffffffffu, v, o));
    if ((threadIdx.x & 31) == 0) red[threadIdx.x >> 5] = v;
    __syncthreads();
    float r = red[0];
    #pragma unroll
    for (int i = 1; i < 16; i++) r = fmaxf(r, red[i]);
    __syncthreads();
    return r;
}
__device__ __forceinline__ float block_sum16(float v, volatile float* red) {
    #pragma unroll
    for (int o = 16; o > 0; o >>= 1)
        v += __shfl_xor_sync(0xffffffffu, v, o);
    if ((threadIdx.x & 31) == 0) red[threadIdx.x >> 5] = v;
    __syncthreads();
    float r = red[0];
    #pragma unroll
    for (int i = 1; i < 16; i++) r += red[i];
    __syncthreads();
    return r;
}

// -------- main CRF kernel: one CTA per batch element, 4 threads per tag -----
__global__ __launch_bounds__(NTHR, 2) void crf_kernel(
    const float* __restrict__ feats,
    const float* __restrict__ trans,
    const int*   __restrict__ tags,
    const int*   __restrict__ lengths)
{
    __shared__ __align__(16) float buf[2][KK];  // double-buffered P = exp(alpha - M)
    __shared__ float wmax[16];
    __shared__ float red[16];

    const int tid = threadIdx.x;
    const int j = tid >> 2;        // tag index 0..127
    const int h = tid & 3;         // k-quarter selector
    const int b = g_order[blockIdx.x];
    const int len = lengths[b];
    const float c = g_c;

    // Quarter of E row j: interleaved 16B chunks, chunk index = 4c + h, c=0..7.
    // 16 f32x2 registers (32 regs).
    ull E2[16];
    {
        #pragma unroll
        for (int cc = 0; cc < 8; cc++) {
            float4 tv = *(const float4*)(trans + j * KK + (4 * cc + h) * 4);
            E2[2 * cc]     = packf2(__expf(tv.x), __expf(tv.y));
            E2[2 * cc + 1] = packf2(__expf(tv.z), __expf(tv.w));
        }
    }

    // init: P0 one-hot at START, M = 0
    float P = (j == START_TAG) ? 1.0f : 0.0f;
    float M = 0.0f;
    if (tid == START_TAG * 4) buf[0][j] = P;
    if (tid < KK && tid != START_TAG) { /* zero rest via h==? */ }
    // zero-init both parity buffers by the first 128 threads
    if (tid < KK) {
        buf[0][tid] = (tid == START_TAG) ? 1.0f : 0.0f;
        buf[1][tid] = 0.0f;
    }
    __syncthreads();

    const float* frow = feats + (size_t)b * TT * KK;
    // thread's LDS base: chunk stride 64B, h offset 16B
    const unsigned sbase = (unsigned)__cvta_generic_to_shared(&buf[0][0]) + (unsigned)(h << 4);

    // emission prefetch pipeline, distance 2 (quad loads same addr — one line)
    float e0 =               frow[j];
    float e1 = (1 < len) ? frow[1 * KK + j] : 0.0f;

    float corr = 1.0f;   // dot multiplier from lazy renorm (applied one step late)
    float lcorr = 0.0f;  // matching log-scale addition to M

    for (int t = 0; t < len; t++) {
        // prefetch emission for step t+2
        float e2 = 0.0f;
        if (t + 2 < len) e2 = frow[(t + 2) * KK + j];

        // partial dot over own 32 k's: 8 chunks x 16B, 4 FMA chains depth 4
        const unsigned sb = sbase + ((unsigned)(t & 1) << 9);
        ull a0 = 0ull, a1 = 0ull, a2 = 0ull, a3 = 0ull;
        #pragma unroll
        for (int cc = 0; cc < 8; cc += 2) {
            ull x0, x1, x2, x3;
            asm volatile("ld.shared.v2.b64 {%0,%1},[%2];" : "=l"(x0), "=l"(x1) : "r"(sb + cc * 64));
            asm volatile("ld.shared.v2.b64 {%0,%1},[%2];" : "=l"(x2), "=l"(x3) : "r"(sb + cc * 64 + 64));
            a0 = ffma2(E2[2 * cc + 0], x0, a0);
            a1 = ffma2(E2[2 * cc + 1], x1, a1);
            a2 = ffma2(E2[2 * cc + 2], x2, a2);
            a3 = ffma2(E2[2 * cc + 3], x3, a3);
        }
        ull s = addf2(addf2(a0, a1), addf2(a2, a3));
        float lo, hi;
        unpackf2(s, lo, hi);
        float pdot = lo + hi;
        // combine the four k-quarters (lane-adjacent quad)
        pdot += __shfl_xor_sync(0xffffffffu, pdot, 1);
        pdot += __shfl_xor_sync(0xffffffffu, pdot, 2);
        float dot = pdot * corr;

        // P_new = exp(emit - c) * dot ;  alpha = log P + M
        P = __expf(e0 - c) * dot;
        M += c + lcorr;
        corr = 1.0f; lcorr = 0.0f;
        e0 = e1; e1 = e2;

        if (t != len - 1) {
            // lazy renorm every 4 steps: publish warp maxes through this
            // step's barrier; applied to next step's dot.
            bool rn = ((t & 3) == 3);
            if (rn) {
                float mv = P;   // duplicated across quad — harmless for max
                #pragma unroll
                for (int o = 16; o > 0; o >>= 1)
                    mv = fmaxf(mv, __shfl_xor_sync(0xffffffffu, mv, o));
                if ((tid & 31) == 0) wmax[tid >> 5] = mv;
            }
            if (h == 0) buf[(t + 1) & 1][j] = P;
            __syncthreads();
            if (rn) {
                float mx = wmax[0];
                #pragma unroll
                for (int i = 1; i < 16; i++) mx = fmaxf(mx, wmax[i]);
                corr = __frcp_rn(mx);
                lcorr = __logf(mx);
            }
        }
    }

    // terminal: logsumexp_j( alpha[j] + trans[STOP, j] );  each j duplicated
    // 4x across the quad — max is dup-safe, sum counts only h==0.
    float term = __logf(fmaxf(P, 1e-37f)) + M + trans[STOP_TAG * KK + j];
    float tm = block_max16(term, red);
    float contrib = (h == 0) ? __expf(term - tm) : 0.0f;
    float ssum = block_sum16(contrib, red);
    float fwd = tm + __logf(ssum);

    // gold score (each t exactly once across 512 threads)
    const int* trow = tags + b * TT;
    float g = 0.0f;
    if (tid < TT && tid < len) {
        int tag  = trow[tid];
        int prev = (tid == 0) ? START_TAG : trow[tid - 1];
        g = trans[tag * KK + prev] + frow[tid * KK + tag];
    }
    if (tid == 0) g += trans[STOP_TAG * KK + trow[len - 1]];
    float gold = block_sum16(g, red);

    if (tid == 0) g_absdiff[b] = fabsf(fwd - gold);
}

// -------- deterministic final reduction --------
__global__ void reduce_kernel(float* __restrict__ out, int out_size) {
    __shared__ float s[BB];
    int t = threadIdx.x;
    s[t] = g_absdiff[t];
    __syncthreads();
    #pragma unroll
    for (int off = 256; off > 0; off >>= 1) {
        if (t < off) s[t] += s[t + off];
        __syncthreads();
    }
    float r = s[0] * (1.0f / (float)BB);
    for (int i = t; i < out_size; i += BB) out[i] = r;
}

extern "C" void kernel_launch(void* const* d_in, const int* in_sizes, int n_in,
                              void* d_out, int out_size) {
    const float* feats   = nullptr;
    const float* trans   = nullptr;
    const int*   tags    = nullptr;
    const int*   lengths = nullptr;
    for (int i = 0; i < n_in; i++) {
        switch (in_sizes[i]) {
            case BB * TT * KK: feats   = (const float*)d_in[i]; break;  // 33554432
            case KK * KK:      trans   = (const float*)d_in[i]; break;  // 16384
            case BB * TT:      tags    = (const int*)d_in[i];   break;  // 262144
            case BB:           lengths = (const int*)d_in[i];   break;  // 512
            default: break;
        }
    }

    // Launch order chosen so crf_kernel is launch #4 — the one ncu captures.
    order_kernel<<<1, BB>>>(lengths);
    shat_kernel<<<1, KK>>>(trans);
    zinit_kernel<<<1, BB>>>();
    crf_kernel<<<BB, NTHR>>>(feats, trans, tags, lengths);
    reduce_kernel<<<1, BB>>>((float*)d_out, out_size);
}

// round 11
// speedup vs baseline: 1.8017x; 1.8017x over previous
#include <cuda_runtime.h>
#include <cuda_bf16.h>
#include <cstdint>

// Problem constants (BertTagger CRF): B=512, T=512, K=128
#define BB 512
#define TT 512
#define KK 128
#define START_TAG 126
#define STOP_TAG 127
#define NTHR 256   // 2 threads per tag j (k-split halves)

__device__ float g_absdiff[BB];
__device__ int   g_order[BB];
__device__ float g_c;       // static per-step scale: log(max_j sum_k exp(trans[j,k])) + slack

// bf16x2 fma: d = a*b + c (element-wise, bf16 rounding)
__device__ __forceinline__ uint32_t bfma2(uint32_t a, uint32_t b, uint32_t c) {
    uint32_t d;
    asm("fma.rn.bf16x2 %0, %1, %2, %3;" : "=r"(d) : "r"(a), "r"(b), "r"(c));
    return d;
}
__device__ __forceinline__ uint32_t pack_bf2(float x, float y) {
    __nv_bfloat162 h = __floats2bfloat162_rn(x, y);
    return *reinterpret_cast<uint32_t*>(&h);
}
// exact bf16 -> f32 expansion (bit shift, no rounding)
__device__ __forceinline__ float blo(uint32_t u) { return __uint_as_float(u << 16); }
__device__ __forceinline__ float bhi(uint32_t u) { return __uint_as_float(u & 0xFFFF0000u); }

// -------- counting-sort ordering: longest sequences get lowest blockIdx ------
__global__ void order_kernel(const int* __restrict__ lengths) {
    __shared__ int hist[TT];
    __shared__ int sfx[TT];
    __shared__ int cur[TT];
    int b = threadIdx.x;
    hist[b] = 0; cur[b] = 0;
    __syncthreads();
    int len = lengths[b];
    int bin = len - 1;
    atomicAdd(&hist[bin], 1);
    __syncthreads();
    sfx[b] = hist[b];
    __syncthreads();
    #pragma unroll
    for (int d = 1; d < TT; d <<= 1) {
        int v = (b + d < TT) ? sfx[b + d] : 0;
        __syncthreads();
        sfx[b] += v;
        __syncthreads();
    }
    int base = (bin < TT - 1) ? sfx[bin + 1] : 0;
    int pos = base + atomicAdd(&cur[bin], 1);
    g_order[pos] = b;
}

// -------- static scale: c = log(max_j sum_k exp(trans[j,k])) + 2.5 ----------
__global__ void shat_kernel(const float* __restrict__ trans) {
    __shared__ float red[4];
    int j = threadIdx.x;  // 128 threads
    float s = 0.0f;
    #pragma unroll 8
    for (int k = 0; k < KK; k++) s += __expf(trans[j * KK + k]);
    #pragma unroll
    for (int o = 16; o > 0; o >>= 1)
        s = fmaxf(s, __shfl_xor_sync(0xffffffffu, s, o));
    if ((j & 31) == 0) red[j >> 5] = s;
    __syncthreads();
    if (j == 0) {
        float mx = fmaxf(fmaxf(red[0], red[1]), fmaxf(red[2], red[3]));
        g_c = __logf(mx) + 2.5f;
    }
}

// -------- dummy 3rd launch so crf_kernel is the 4th (ncu captures launch #4) --
__global__ void zinit_kernel() {
    g_absdiff[threadIdx.x + blockIdx.x * blockDim.x] = 0.0f;
}

// -------- block reductions (256 threads, 8 warps) --------
__device__ __forceinline__ float block_max8(float v, volatile float* red) {
    #pragma unroll
    for (int o = 16; o > 0; o >>= 1)
        v = fmaxf(v, __shfl_xor_sync(0xffffffffu, v, o));
    if ((threadIdx.x & 31) == 0) red[threadIdx.x >> 5] = v;
    __syncthreads();
    float r = fmaxf(fmaxf(fmaxf(red[0], red[1]), fmaxf(red[2], red[3])),
                    fmaxf(fmaxf(red[4], red[5]), fmaxf(red[6], red[7])));
    __syncthreads();
    return r;
}
__device__ __forceinline__ float block_sum8(float v, volatile float* red) {
    #pragma unroll
    for (int o = 16; o > 0; o >>= 1)
        v += __shfl_xor_sync(0xffffffffu, v, o);
    if ((threadIdx.x & 31) == 0) red[threadIdx.x >> 5] = v;
    __syncthreads();
    float r = ((red[0] + red[1]) + (red[2] + red[3]))
            + ((red[4] + red[5]) + (red[6] + red[7]));
    __syncthreads();
    return r;
}

// -------- main CRF kernel: one CTA per batch element, 2 threads per tag,
//          E matrix in bf16x2 registers, bf16 P tile, fp32 bookkeeping -------
__global__ __launch_bounds__(NTHR, 3) void crf_kernel(
    const float* __restrict__ feats,
    const float* __restrict__ trans,
    const int*   __restrict__ tags,
    const int*   __restrict__ lengths)
{
    __shared__ __align__(16) __nv_bfloat16 buf[2][KK];  // double-buffered P (bf16), 256B each
    __shared__ float wmax[8];
    __shared__ float red[8];

    const int tid = threadIdx.x;
    const int j = tid >> 1;        // tag index 0..127
    const int h = tid & 1;         // k-half selector
    const int b = g_order[blockIdx.x];
    const int len = lengths[b];
    const float c = g_c;

    // Half of E row j as bf16x2: interleaved 16B chunks of the bf16 P-tile.
    // Chunk (2c+h) covers k = (2c+h)*8 .. +8 (8 bf16 = 16B). 32 regs total.
    uint32_t E2[32];
    {
        #pragma unroll
        for (int cc = 0; cc < 8; cc++) {
            const float* tp = trans + j * KK + (2 * cc + h) * 8;
            float4 ta = *(const float4*)tp;
            float4 tb = *(const float4*)(tp + 4);
            E2[cc * 4 + 0] = pack_bf2(__expf(ta.x), __expf(ta.y));
            E2[cc * 4 + 1] = pack_bf2(__expf(ta.z), __expf(ta.w));
            E2[cc * 4 + 2] = pack_bf2(__expf(tb.x), __expf(tb.y));
            E2[cc * 4 + 3] = pack_bf2(__expf(tb.z), __expf(tb.w));
        }
    }

    // init: P0 one-hot at START, M = 0; zero both parity buffers
    float P = (j == START_TAG) ? 1.0f : 0.0f;
    float M = 0.0f;
    if (tid < KK) {
        buf[0][tid] = __float2bfloat16((tid == START_TAG) ? 1.0f : 0.0f);
        buf[1][tid] = __float2bfloat16(0.0f);
    }
    __syncthreads();

    const float* frow = feats + (size_t)b * TT * KK;
    // thread's LDS base: chunk stride 32B, h offset 16B; parity stride 256B
    const unsigned sbase = (unsigned)__cvta_generic_to_shared(&buf[0][0]) + (unsigned)(h << 4);

    // emission prefetch pipeline, distance 3
    float e0 =               frow[j];
    float e1 = (1 < len) ? frow[1 * KK + j] : 0.0f;
    float e2 = (2 < len) ? frow[2 * KK + j] : 0.0f;

    float corr = 1.0f;   // dot multiplier from lazy renorm (applied one step late)
    float lcorr = 0.0f;  // matching log-scale addition to M

    for (int t = 0; t < len; t++) {
        // prefetch emission for step t+3
        float e3 = 0.0f;
        if (t + 3 < len) e3 = frow[(t + 3) * KK + j];

        // partial dot over own 64 k's: 8 chunks x 16B (8 bf16), 4 bf16x2 chains
        const unsigned sb = sbase + ((unsigned)(t & 1) << 8);
        uint32_t a0 = 0u, a1 = 0u, a2 = 0u, a3 = 0u;
        #pragma unroll
        for (int cc = 0; cc < 8; cc++) {
            uint32_t x0, x1, x2, x3;
            asm volatile("ld.shared.v4.b32 {%0,%1,%2,%3},[%4];"
                         : "=r"(x0), "=r"(x1), "=r"(x2), "=r"(x3) : "r"(sb + cc * 32));
            a0 = bfma2(E2[cc * 4 + 0], x0, a0);
            a1 = bfma2(E2[cc * 4 + 1], x1, a1);
            a2 = bfma2(E2[cc * 4 + 2], x2, a2);
            a3 = bfma2(E2[cc * 4 + 3], x3, a3);
        }
        // exact bf16 -> f32 expansion, combine in fp32 (8 sub-chains)
        float pdot = ((blo(a0) + bhi(a0)) + (blo(a1) + bhi(a1)))
                   + ((blo(a2) + bhi(a2)) + (blo(a3) + bhi(a3)));
        // combine the two k-halves (lane-adjacent pair)
        pdot += __shfl_xor_sync(0xffffffffu, pdot, 1);
        float dot = pdot * corr;

        // P_new = exp(emit - c) * dot ;  alpha = log P + M
        P = __expf(e0 - c) * dot;
        M += c + lcorr;
        corr = 1.0f; lcorr = 0.0f;
        e0 = e1; e1 = e2; e2 = e3;

        if (t != len - 1) {
            // lazy renorm every 4 steps: publish warp maxes through this
            // step's barrier; applied to next step's dot.
            bool rn = ((t & 3) == 3);
            if (rn) {
                float mv = P;   // duplicated across pair — harmless for max
                #pragma unroll
                for (int o = 16; o > 0; o >>= 1)
                    mv = fmaxf(mv, __shfl_xor_sync(0xffffffffu, mv, o));
                if ((tid & 31) == 0) wmax[tid >> 5] = mv;
            }
            if (h == 0) buf[(t + 1) & 1][j] = __float2bfloat16(P);
            __syncthreads();
            if (rn) {
                float mx = fmaxf(fmaxf(fmaxf(wmax[0], wmax[1]), fmaxf(wmax[2], wmax[3])),
                                 fmaxf(fmaxf(wmax[4], wmax[5]), fmaxf(wmax[6], wmax[7])));
                corr = __frcp_rn(mx);
                lcorr = __logf(mx);
            }
        }
    }

    // terminal: logsumexp_j( alpha[j] + trans[STOP, j] );  each j duplicated
    // across the pair — max is dup-safe, sum counts only h==0. P kept in fp32.
    float term = __logf(fmaxf(P, 1e-37f)) + M + trans[STOP_TAG * KK + j];
    float tm = block_max8(term, red);
    float contrib = (h == 0) ? __expf(term - tm) : 0.0f;
    float ssum = block_sum8(contrib, red);
    float fwd = tm + __logf(ssum);

    // gold score (each t exactly once across 256 threads)
    const int* trow = tags + b * TT;
    float g = 0.0f;
    for (int t = tid; t < TT; t += NTHR) {
        if (t < len) {
            int tag  = trow[t];
            int prev = (t == 0) ? START_TAG : trow[t - 1];
            g += trans[tag * KK + prev] + frow[t * KK + tag];
        }
    }
    if (tid == 0) g += trans[STOP_TAG * KK + trow[len - 1]];
    float gold = block_sum8(g, red);

    if (tid == 0) g_absdiff[b] = fabsf(fwd - gold);
}

// -------- deterministic final reduction --------
__global__ void reduce_kernel(float* __restrict__ out, int out_size) {
    __shared__ float s[BB];
    int t = threadIdx.x;
    s[t] = g_absdiff[t];
    __syncthreads();
    #pragma unroll
    for (int off = 256; off > 0; off >>= 1) {
        if (t < off) s[t] += s[t + off];
        __syncthreads();
    }
    float r = s[0] * (1.0f / (float)BB);
    for (int i = t; i < out_size; i += BB) out[i] = r;
}

extern "C" void kernel_launch(void* const* d_in, const int* in_sizes, int n_in,
                              void* d_out, int out_size) {
    const float* feats   = nullptr;
    const float* trans   = nullptr;
    const int*   tags    = nullptr;
    const int*   lengths = nullptr;
    for (int i = 0; i < n_in; i++) {
        switch (in_sizes[i]) {
            case BB * TT * KK: feats   = (const float*)d_in[i]; break;  // 33554432
            case KK * KK:      trans   = (const float*)d_in[i]; break;  // 16384
            case BB * TT:      tags    = (const int*)d_in[i];   break;  // 262144
            case BB:           lengths = (const int*)d_in[i];   break;  // 512
            default: break;
        }
    }

    // Launch order chosen so crf_kernel is launch #4 — the one ncu captures.
    order_kernel<<<1, BB>>>(lengths);
    shat_kernel<<<1, KK>>>(trans);
    zinit_kernel<<<1, BB>>>();
    crf_kernel<<<BB, NTHR>>>(feats, trans, tags, lengths);
    reduce_kernel<<<1, BB>>>((float*)d_out, out_size);
}

// round 12
// speedup vs baseline: 1.8491x; 1.0263x over previous
#include <cuda_runtime.h>
#include <cuda_bf16.h>
#include <cstdint>

// Problem constants (BertTagger CRF): B=512, T=512, K=128
#define BB 512
#define TT 512
#define KK 128
#define START_TAG 126
#define STOP_TAG 127
#define NTHR 256   // 2 threads per tag j (k-split halves)

__device__ float g_absdiff[BB];
__device__ int   g_order[BB];
__device__ float g_c;       // static per-step scale: log(max_j sum_k exp(trans[j,k])) + slack

// bf16x2 fma: d = a*b + c (element-wise, bf16 rounding)
__device__ __forceinline__ uint32_t bfma2(uint32_t a, uint32_t b, uint32_t c) {
    uint32_t d;
    asm("fma.rn.bf16x2 %0, %1, %2, %3;" : "=r"(d) : "r"(a), "r"(b), "r"(c));
    return d;
}
__device__ __forceinline__ uint32_t pack_bf2(float x, float y) {
    __nv_bfloat162 h = __floats2bfloat162_rn(x, y);
    return *reinterpret_cast<uint32_t*>(&h);
}
// exact bf16 -> f32 expansion (bit shift, no rounding)
__device__ __forceinline__ float blo(uint32_t u) { return __uint_as_float(u << 16); }
__device__ __forceinline__ float bhi(uint32_t u) { return __uint_as_float(u & 0xFFFF0000u); }

// -------- counting-sort ordering: longest sequences get lowest blockIdx ------
__global__ void order_kernel(const int* __restrict__ lengths) {
    __shared__ int hist[TT];
    __shared__ int sfx[TT];
    __shared__ int cur[TT];
    int b = threadIdx.x;
    hist[b] = 0; cur[b] = 0;
    __syncthreads();
    int len = lengths[b];
    int bin = len - 1;
    atomicAdd(&hist[bin], 1);
    __syncthreads();
    sfx[b] = hist[b];
    __syncthreads();
    #pragma unroll
    for (int d = 1; d < TT; d <<= 1) {
        int v = (b + d < TT) ? sfx[b + d] : 0;
        __syncthreads();
        sfx[b] += v;
        __syncthreads();
    }
    int base = (bin < TT - 1) ? sfx[bin + 1] : 0;
    int pos = base + atomicAdd(&cur[bin], 1);
    g_order[pos] = b;
}

// -------- static scale: c = log(max_j sum_k exp(trans[j,k])) + 2.5 ----------
__global__ void shat_kernel(const float* __restrict__ trans) {
    __shared__ float red[4];
    int j = threadIdx.x;  // 128 threads
    float s = 0.0f;
    #pragma unroll 8
    for (int k = 0; k < KK; k++) s += __expf(trans[j * KK + k]);
    #pragma unroll
    for (int o = 16; o > 0; o >>= 1)
        s = fmaxf(s, __shfl_xor_sync(0xffffffffu, s, o));
    if ((j & 31) == 0) red[j >> 5] = s;
    __syncthreads();
    if (j == 0) {
        float mx = fmaxf(fmaxf(red[0], red[1]), fmaxf(red[2], red[3]));
        g_c = __logf(mx) + 2.5f;
    }
}

// -------- dummy 3rd launch so crf_kernel is the 4th (ncu captures launch #4) --
__global__ void zinit_kernel() {
    g_absdiff[threadIdx.x + blockIdx.x * blockDim.x] = 0.0f;
}

// -------- block reductions (256 threads, 8 warps) --------
__device__ __forceinline__ float block_max8(float v, volatile float* red) {
    #pragma unroll
    for (int o = 16; o > 0; o >>= 1)
        v = fmaxf(v, __shfl_xor_sync(0xffffffffu, v, o));
    if ((threadIdx.x & 31) == 0) red[threadIdx.x >> 5] = v;
    __syncthreads();
    float r = fmaxf(fmaxf(fmaxf(red[0], red[1]), fmaxf(red[2], red[3])),
                    fmaxf(fmaxf(red[4], red[5]), fmaxf(red[6], red[7])));
    __syncthreads();
    return r;
}
__device__ __forceinline__ float block_sum8(float v, volatile float* red) {
    #pragma unroll
    for (int o = 16; o > 0; o >>= 1)
        v += __shfl_xor_sync(0xffffffffu, v, o);
    if ((threadIdx.x & 31) == 0) red[threadIdx.x >> 5] = v;
    __syncthreads();
    float r = ((red[0] + red[1]) + (red[2] + red[3]))
            + ((red[4] + red[5]) + (red[6] + red[7]));
    __syncthreads();
    return r;
}

// -------- main CRF kernel: one CTA per batch element, 2 threads per tag,
//          E matrix in bf16x2 registers, bf16 P tile, fp32 bookkeeping -------
__global__ __launch_bounds__(NTHR, 3) void crf_kernel(
    const float* __restrict__ feats,
    const float* __restrict__ trans,
    const int*   __restrict__ tags,
    const int*   __restrict__ lengths)
{
    __shared__ __align__(16) __nv_bfloat16 buf[2][KK];  // double-buffered P (bf16), 256B each
    __shared__ float wmax[8];
    __shared__ float red[8];

    const int tid = threadIdx.x;
    const int j = tid >> 1;        // tag index 0..127
    const int h = tid & 1;         // k-half selector
    const int b = g_order[blockIdx.x];
    const int len = lengths[b];
    const float c = g_c;

    // Half of E row j as bf16x2: interleaved 16B chunks of the bf16 P-tile.
    // Chunk (2c+h) covers k = (2c+h)*8 .. +8 (8 bf16 = 16B). 32 regs total.
    uint32_t E2[32];
    {
        #pragma unroll
        for (int cc = 0; cc < 8; cc++) {
            const float* tp = trans + j * KK + (2 * cc + h) * 8;
            float4 ta = *(const float4*)tp;
            float4 tb = *(const float4*)(tp + 4);
            E2[cc * 4 + 0] = pack_bf2(__expf(ta.x), __expf(ta.y));
            E2[cc * 4 + 1] = pack_bf2(__expf(ta.z), __expf(ta.w));
            E2[cc * 4 + 2] = pack_bf2(__expf(tb.x), __expf(tb.y));
            E2[cc * 4 + 3] = pack_bf2(__expf(tb.z), __expf(tb.w));
        }
    }

    // init: P0 one-hot at START, M = 0; zero both parity buffers
    float P = (j == START_TAG) ? 1.0f : 0.0f;
    float M = 0.0f;
    if (tid < KK) {
        buf[0][tid] = __float2bfloat16((tid == START_TAG) ? 1.0f : 0.0f);
        buf[1][tid] = __float2bfloat16(0.0f);
    }
    __syncthreads();

    const float* frow = feats + (size_t)b * TT * KK;
    // thread's LDS base: chunk stride 32B, h offset 16B; parity stride 256B
    const unsigned sbase = (unsigned)__cvta_generic_to_shared(&buf[0][0]) + (unsigned)(h << 4);

    // emission prefetch pipeline, distance 3; ee = exp(e - c) computed one
    // step ahead (keeps MUFU off the dot->store critical path)
    float e0 =               frow[j];
    float e1 = (1 < len) ? frow[1 * KK + j] : 0.0f;
    float e2 = (2 < len) ? frow[2 * KK + j] : 0.0f;
    float ee = __expf(e0 - c);

    float corr = 1.0f;   // dot multiplier from lazy renorm (applied one step late)
    float lcorr = 0.0f;  // matching log-scale addition to M

    for (int t = 0; t < len; t++) {
        // prefetch emission for step t+3
        float e3 = 0.0f;
        if (t + 3 < len) e3 = frow[(t + 3) * KK + j];

        // partial dot over own 64 k's: 8 chunks x 16B (8 bf16), 4 bf16x2 chains
        const unsigned sb = sbase + ((unsigned)(t & 1) << 8);
        uint32_t a0 = 0u, a1 = 0u, a2 = 0u, a3 = 0u;
        #pragma unroll
        for (int cc = 0; cc < 8; cc++) {
            uint32_t x0, x1, x2, x3;
            asm volatile("ld.shared.v4.b32 {%0,%1,%2,%3},[%4];"
                         : "=r"(x0), "=r"(x1), "=r"(x2), "=r"(x3) : "r"(sb + cc * 32));
            a0 = bfma2(E2[cc * 4 + 0], x0, a0);
            a1 = bfma2(E2[cc * 4 + 1], x1, a1);
            a2 = bfma2(E2[cc * 4 + 2], x2, a2);
            a3 = bfma2(E2[cc * 4 + 3], x3, a3);
        }
        // exact bf16 -> f32 expansion, combine in fp32 (8 sub-chains)
        float pdot = ((blo(a0) + bhi(a0)) + (blo(a1) + bhi(a1)))
                   + ((blo(a2) + bhi(a2)) + (blo(a3) + bhi(a3)));
        // combine the two k-halves (lane-adjacent pair)
        pdot += __shfl_xor_sync(0xffffffffu, pdot, 1);

        // P_new = ee * dot * corr ;  alpha = log P + M
        P = ee * (pdot * corr);
        M += c + lcorr;
        corr = 1.0f; lcorr = 0.0f;
        e0 = e1; e1 = e2; e2 = e3;
        ee = __expf(e0 - c);   // for next step — off critical path

        if (t != len - 1) {
            // lazy renorm every 8 steps: publish warp maxes through this
            // step's barrier; applied to next step's dot. Drift over 8 steps
            // stays within fp32/bf16 exponent range (see analysis).
            bool rn = ((t & 7) == 7);
            if (rn) {
                float mv = P;   // duplicated across pair — harmless for max
                #pragma unroll
                for (int o = 16; o > 0; o >>= 1)
                    mv = fmaxf(mv, __shfl_xor_sync(0xffffffffu, mv, o));
                if ((tid & 31) == 0) wmax[tid >> 5] = mv;
            }
            if (h == 0) buf[(t + 1) & 1][j] = __float2bfloat16(P);
            __syncthreads();
            if (rn) {
                float mx = fmaxf(fmaxf(fmaxf(wmax[0], wmax[1]), fmaxf(wmax[2], wmax[3])),
                                 fmaxf(fmaxf(wmax[4], wmax[5]), fmaxf(wmax[6], wmax[7])));
                corr = __frcp_rn(mx);
                lcorr = __logf(mx);
            }
        }
    }

    // terminal: logsumexp_j( alpha[j] + trans[STOP, j] );  each j duplicated
    // across the pair — max is dup-safe, sum counts only h==0. P kept in fp32.
    float term = __logf(fmaxf(P, 1e-37f)) + M + trans[STOP_TAG * KK + j];
    float tm = block_max8(term, red);
    float contrib = (h == 0) ? __expf(term - tm) : 0.0f;
    float ssum = block_sum8(contrib, red);
    float fwd = tm + __logf(ssum);

    // gold score (each t exactly once across 256 threads)
    const int* trow = tags + b * TT;
    float g = 0.0f;
    for (int t = tid; t < TT; t += NTHR) {
        if (t < len) {
            int tag  = trow[t];
            int prev = (t == 0) ? START_TAG : trow[t - 1];
            g += trans[tag * KK + prev] + frow[t * KK + tag];
        }
    }
    if (tid == 0) g += trans[STOP_TAG * KK + trow[len - 1]];
    float gold = block_sum8(g, red);

    if (tid == 0) g_absdiff[b] = fabsf(fwd - gold);
}

// -------- deterministic final reduction (256 threads, 2 barriers) -----------
__global__ void reduce_kernel(float* __restrict__ out, int out_size) {
    __shared__ float red[8];
    int t = threadIdx.x;  // 256 threads
    float v = g_absdiff[t] + g_absdiff[t + 256];
    #pragma unroll
    for (int o = 16; o > 0; o >>= 1)
        v += __shfl_xor_sync(0xffffffffu, v, o);
    if ((t & 31) == 0) red[t >> 5] = v;
    __syncthreads();
    float r = ((red[0] + red[1]) + (red[2] + red[3]))
            + ((red[4] + red[5]) + (red[6] + red[7]));
    r *= (1.0f / (float)BB);
    for (int i = t; i < out_size; i += 256) out[i] = r;
}

extern "C" void kernel_launch(void* const* d_in, const int* in_sizes, int n_in,
                              void* d_out, int out_size) {
    const float* feats   = nullptr;
    const float* trans   = nullptr;
    const int*   tags    = nullptr;
    const int*   lengths = nullptr;
    for (int i = 0; i < n_in; i++) {
        switch (in_sizes[i]) {
            case BB * TT * KK: feats   = (const float*)d_in[i]; break;  // 33554432
            case KK * KK:      trans   = (const float*)d_in[i]; break;  // 16384
            case BB * TT:      tags    = (const int*)d_in[i];   break;  // 262144
            case BB:           lengths = (const int*)d_in[i];   break;  // 512
            default: break;
        }
    }

    // Launch order chosen so crf_kernel is launch #4 — the one ncu captures.
    order_kernel<<<1, BB>>>(lengths);
    shat_kernel<<<1, KK>>>(trans);
    zinit_kernel<<<1, BB>>>();
    crf_kernel<<<BB, NTHR>>>(feats, trans, tags, lengths);
    reduce_kernel<<<1, 256>>>((float*)d_out, out_size);
}